// round 6
// baseline (speedup 1.0000x reference)
#include <cuda_runtime.h>
#include <cstdint>

// Problem constants
#define BATCH   16
#define TLEN    4096
#define DIMX    256
#define HID     128
#define G3      384
#define NLAYER  3
#define MROWS   (BATCH * TLEN)      // 65536

// Persistent-kernel structure
#define NBLK    148
#define RECB    32
#define GEMB    (NBLK - RECB)       // 116

// GEMM tiling
#define BM      128
#define BN      96
#define BK      16
#define NT_PER  (G3 / BN)           // 4
#define NCHUNK  (TLEN / BM)         // 32
#define TILES_PER_LAYER (2 * BATCH * NCHUNK * NT_PER)   // 4096

// -------- scratch (device globals; no runtime allocation allowed) ----------
__device__ float g_xgA[(size_t)2 * MROWS * G3];
__device__ float g_xgB[(size_t)2 * MROWS * G3];
__device__ float g_yA[(size_t)MROWS * DIMX];
__device__ float g_yB[(size_t)MROWS * DIMX];
__device__ unsigned g_fwdsteps[NLAYER][BATCH];
__device__ unsigned g_bwdsteps[NLAYER][BATCH];
__device__ unsigned g_xgready[NLAYER][2][BATCH][NCHUNK];

// ---------------- f32x2 packed helpers (Blackwell sm_103a) -----------------
__device__ __forceinline__ unsigned long long pk2(float lo, float hi) {
    unsigned long long r;
    asm("mov.b64 %0, {%1, %2};" : "=l"(r) : "f"(lo), "f"(hi));
    return r;
}
__device__ __forceinline__ void up2(unsigned long long v, float& lo, float& hi) {
    asm("mov.b64 {%0, %1}, %2;" : "=f"(lo), "=f"(hi) : "l"(v));
}
__device__ __forceinline__ unsigned long long fma2(unsigned long long a,
                                                   unsigned long long b,
                                                   unsigned long long c) {
    unsigned long long d;
    asm("fma.rn.f32x2 %0, %1, %2, %3;" : "=l"(d) : "l"(a), "l"(b), "l"(c));
    return d;
}
__device__ __forceinline__ unsigned long long fadd2(unsigned long long a,
                                                    unsigned long long b) {
    unsigned long long d;
    asm("add.rn.f32x2 %0, %1, %2;" : "=l"(d) : "l"(a), "l"(b));
    return d;
}
__device__ __forceinline__ float ex2f(float x) {
    float y; asm("ex2.approx.f32 %0, %1;" : "=f"(y) : "f"(x)); return y;
}
__device__ __forceinline__ float rcpf(float x) {
    float y; asm("rcp.approx.f32 %0, %1;" : "=f"(y) : "f"(x)); return y;
}
// sigmoid(x) = 1/(1+e^-x) : mul, ex2, add, rcp
__device__ __forceinline__ float sigmf(float x) {
    return rcpf(1.0f + ex2f(x * -1.4426950408889634f));
}
// tanh(x) = 1 - 2/(e^{2x}+1) : mul, ex2, add, rcp, fma  (correct at +-inf)
__device__ __forceinline__ float tanhf_(float x) {
    return fmaf(-2.0f, rcpf(1.0f + ex2f(x * 2.8853900817779268f)), 1.0f);
}
__device__ __forceinline__ unsigned ldv(const unsigned* p) {
    return *(volatile const unsigned*)p;
}

// -------------------------- flag reset kernel ------------------------------
__global__ void reset_flags() {
    int i = blockIdx.x * blockDim.x + threadIdx.x;
    unsigned* r = &g_xgready[0][0][0][0];
    const int nr = NLAYER * 2 * BATCH * NCHUNK;
    if (i < nr) r[i] = 0;
    if (i < NLAYER * BATCH) {
        (&g_fwdsteps[0][0])[i] = 0;
        (&g_bwdsteps[0][0])[i] = 0;
    }
}

// ---------------- recurrence: one layer, direction templated ---------------
template <int D>
__device__ __forceinline__ void rec_layer(
    const float* __restrict__ xgb,    // xg base for (d,b): [TLEN][G3]
    float* __restrict__ ybase,        // y base for (d,b) at t=0, col jj
    const float* __restrict__ Wd,     // Wh for (l,d): [128][384]
    const float* __restrict__ bhd,    // bias for (l,d): [384]
    const unsigned* __restrict__ rdy, // chunk-ready flags [NCHUNK]
    volatile unsigned* prog,          // progress counter to publish
    int j, int gate, int jj,
    float* sh_h, float* sh_g)
{
    constexpr int XS = D ? -G3 : G3;      // compile-time strides
    constexpr int YS = D ? -DIMX : DIMX;
    constexpr int T0 = D ? (TLEN - 1) : 0;

    const float bias = bhd[j];

    unsigned long long w2[64];
#pragma unroll
    for (int i = 0; i < 64; i++)
        w2[i] = pk2(Wd[(2 * i) * G3 + j], Wd[(2 * i + 1) * G3 + j]);

    if (j < HID) sh_h[j] = 0.0f;

    // wait for the first chunk this direction consumes
    if (j == 0) {
        const int c0 = D ? (NCHUNK - 1) : 0;
        while (ldv(&rdy[c0]) < NT_PER) __nanosleep(64);
    }
    __syncthreads();
    __threadfence();

    const float* xp = xgb + (size_t)T0 * G3 + j;
    float* yp = ybase + (long)T0 * DIMX;
    float x0 = __ldg(xp);
    float hp = 0.0f;       // gate-2 register copy of h[jj]
    unsigned done = 0;

#define GRU_STEP(PFOFF)                                                       \
    {                                                                         \
        float x1 = __ldg(xp + (PFOFF));                                       \
        unsigned long long a0 = pk2(bias, 0.0f), a1 = 0ULL;                   \
        const ulonglong2* h2 = (const ulonglong2*)sh_h;                       \
        _Pragma("unroll")                                                     \
        for (int i = 0; i < 32; i++) {                                        \
            ulonglong2 hv = h2[i];                                            \
            a0 = fma2(hv.x, w2[2 * i], a0);                                   \
            a1 = fma2(hv.y, w2[2 * i + 1], a1);                               \
        }                                                                     \
        a0 = fadd2(a0, a1);                                                   \
        float lo_, hi_;                                                       \
        up2(a0, lo_, hi_);                                                    \
        const float q = lo_ + hi_;   /* hdot + bias */                        \
        if (gate < 2) {                                                       \
            sh_g[gate * HID + jj] = sigmf(x0 + q);                            \
            asm volatile("bar.arrive 1, 384;" ::: "memory");                  \
        } else {                                                              \
            asm volatile("bar.sync 1, 384;" ::: "memory");                    \
            float r_ = sh_g[jj];                                              \
            float z_ = sh_g[HID + jj];                                        \
            float n_ = tanhf_(fmaf(r_, q, x0));                               \
            float hn = fmaf(z_, hp - n_, n_);                                 \
            hp = hn;                                                          \
            sh_h[jj] = hn;                                                    \
            *yp = hn;                                                         \
        }                                                                     \
        __syncthreads();                                                      \
        x0 = x1;                                                              \
        xp += XS;                                                             \
        yp += YS;                                                             \
    }

    for (int c = 0; c < NCHUNK; c++) {
        // 127 steps whose distance-1 prefetch stays inside chunk c
        for (int u = 0; u < 127; u++) {
            GRU_STEP(XS)
        }
        if (c < NCHUNK - 1) {
            // last step of the chunk prefetches into chunk c+1: wait first
            const int cn = D ? (NCHUNK - 2 - c) : (c + 1);
            if (j == 0) {
                while (ldv(&rdy[cn]) < NT_PER) __nanosleep(64);
            }
            __syncthreads();
            __threadfence();
            GRU_STEP(XS)
        } else {
            GRU_STEP(0)   // clamp: reload current (value unused)
        }
        done += BM;
        if (j == 0) {
            __threadfence();
            *prog = done;
        }
    }
#undef GRU_STEP
}

// ------------------------- persistent fused kernel -------------------------
__global__ void __launch_bounds__(384, 1)
fused_birnn(const float* __restrict__ xin,
            const float* __restrict__ Wi,   // [3][2][256][384]
            const float* __restrict__ Wh,   // [3][2][128][384]
            const float* __restrict__ bh,   // [3][2][384]
            float* __restrict__ out) {
    __shared__ __align__(16) float sh_As[2][BK][BM + 4];
    __shared__ __align__(16) unsigned long long sh_Bs[2][BK][BN];
    __shared__ __align__(16) float sh_h[HID];
    __shared__ __align__(16) float sh_g[2 * HID];   // [r | z]

    const int tid = threadIdx.x;

    if (blockIdx.x < RECB) {
        // ================= RECURRENCE ROLE (blocks 0..31) ==================
        const int d = blockIdx.x >> 4;
        const int b = blockIdx.x & 15;
        const int j = tid;
        const int gate = j >> 7;
        const int jj = j & 127;

        for (int l = 0; l < NLAYER; l++) {
            const float* Wd = Wh + (size_t)(l * 2 + d) * HID * G3;
            const float* bhd = bh + (size_t)(l * 2 + d) * G3;
            const float* xgbuf = (l == 1) ? g_xgB : g_xgA;
            const float* xgb = xgbuf + ((size_t)d * MROWS + (size_t)b * TLEN) * G3;
            float* yo = (l == 0) ? g_yA : (l == 1) ? g_yB : out;
            float* ybase = yo + (size_t)b * TLEN * DIMX + d * HID + jj;
            const unsigned* rdy = &g_xgready[l][d][b][0];
            volatile unsigned* prog = d ? &g_bwdsteps[l][b] : &g_fwdsteps[l][b];

            if (d == 0)
                rec_layer<0>(xgb, ybase, Wd, bhd, rdy, prog, j, gate, jj,
                             sh_h, sh_g);
            else
                rec_layer<1>(xgb, ybase, Wd, bhd, rdy, prog, j, gate, jj,
                             sh_h, sh_g);
        }
    } else {
        // =================== GEMM ROLE (blocks 32..147) ====================
        const int gid = blockIdx.x - RECB;
        const int ty8 = (tid / 24) * 8;
        const int tx4 = (tid % 24) * 4;
        const int arow = tid >> 2;
        const int ak = (tid & 3) << 2;
        const int brow = tid / 24;
        const int bc = (tid % 24) * 4;

        for (int l = 0; l < NLAYER; l++) {
            const float* Asrc = (l == 0) ? xin : (l == 1) ? g_yA : g_yB;
            float* xgdst = (l == 1) ? g_xgB : g_xgA;
            const float* Wl = Wi + (size_t)l * 2 * DIMX * G3;

            for (int rank = gid; rank < TILES_PER_LAYER; rank += GEMB) {
                const int o = rank >> 7;
                const int rem = rank & 127;
                const int dir = rem >> 6;
                const int b = (rem >> 2) & 15;
                const int nt = rem & 3;
                int ci;
                if (l == 0)
                    ci = (o & 1) ? (NCHUNK - 1 - (o >> 1)) : (o >> 1);
                else
                    ci = (o & 1) ? (NCHUNK / 2 + (o >> 1))
                                 : (NCHUNK / 2 - 1 - (o >> 1));

                if (l > 0) {
                    if (tid == 0) {
                        unsigned needf = (unsigned)((ci + 1) * BM);
                        unsigned needb = (unsigned)(TLEN - ci * BM);
                        while (ldv(&g_fwdsteps[l - 1][b]) < needf) __nanosleep(128);
                        while (ldv(&g_bwdsteps[l - 1][b]) < needb) __nanosleep(128);
                    }
                    __syncthreads();
                    __threadfence();
                }

                const float* At = Asrc + ((size_t)b * TLEN + (size_t)ci * BM) * DIMX;
                const float* Bt = Wl + (size_t)dir * DIMX * G3 + nt * BN;
                float* Ct = xgdst + (size_t)dir * MROWS * G3 +
                            ((size_t)b * TLEN + (size_t)ci * BM) * G3 + nt * BN;

                unsigned long long acc[4][4];
#pragma unroll
                for (int i = 0; i < 4; i++)
#pragma unroll
                    for (int q = 0; q < 4; q++) acc[i][q] = 0ULL;

                float4 a0r = *(const float4*)&At[(size_t)arow * DIMX + ak];
                float4 a1r = make_float4(0.f, 0.f, 0.f, 0.f);
                if (tid < 128)
                    a1r = *(const float4*)&At[(size_t)(arow + 96) * DIMX + ak];
                float4 b0r = *(const float4*)&Bt[(size_t)brow * G3 + bc];

                sh_As[0][ak + 0][arow] = a0r.x;
                sh_As[0][ak + 1][arow] = a0r.y;
                sh_As[0][ak + 2][arow] = a0r.z;
                sh_As[0][ak + 3][arow] = a0r.w;
                if (tid < 128) {
                    sh_As[0][ak + 0][arow + 96] = a1r.x;
                    sh_As[0][ak + 1][arow + 96] = a1r.y;
                    sh_As[0][ak + 2][arow + 96] = a1r.z;
                    sh_As[0][ak + 3][arow + 96] = a1r.w;
                }
                {
                    ulonglong2 bp0, bp1;
                    bp0.x = pk2(b0r.x, b0r.x); bp0.y = pk2(b0r.y, b0r.y);
                    bp1.x = pk2(b0r.z, b0r.z); bp1.y = pk2(b0r.w, b0r.w);
                    *(ulonglong2*)&sh_Bs[0][brow][bc] = bp0;
                    *(ulonglong2*)&sh_Bs[0][brow][bc + 2] = bp1;
                }
                __syncthreads();

                for (int cc = 0; cc < DIMX / BK; cc++) {
                    const int cur = cc & 1;
                    if (cc < DIMX / BK - 1) {
                        const int k0 = (cc + 1) * BK;
                        a0r = *(const float4*)&At[(size_t)arow * DIMX + k0 + ak];
                        if (tid < 128)
                            a1r = *(const float4*)&At[(size_t)(arow + 96) * DIMX + k0 + ak];
                        b0r = *(const float4*)&Bt[(size_t)(k0 + brow) * G3 + bc];
                    }
#pragma unroll
                    for (int k = 0; k < BK; k++) {
                        const float* Ak = &sh_As[cur][k][ty8];
                        ulonglong2 av0 = *(const ulonglong2*)(Ak);
                        ulonglong2 av1 = *(const ulonglong2*)(Ak + 4);
                        const unsigned long long* Bk = &sh_Bs[cur][k][tx4];
                        ulonglong2 bv0 = *(const ulonglong2*)(Bk);
                        ulonglong2 bv1 = *(const ulonglong2*)(Bk + 2);
                        acc[0][0] = fma2(av0.x, bv0.x, acc[0][0]);
                        acc[0][1] = fma2(av0.x, bv0.y, acc[0][1]);
                        acc[0][2] = fma2(av0.x, bv1.x, acc[0][2]);
                        acc[0][3] = fma2(av0.x, bv1.y, acc[0][3]);
                        acc[1][0] = fma2(av0.y, bv0.x, acc[1][0]);
                        acc[1][1] = fma2(av0.y, bv0.y, acc[1][1]);
                        acc[1][2] = fma2(av0.y, bv1.x, acc[1][2]);
                        acc[1][3] = fma2(av0.y, bv1.y, acc[1][3]);
                        acc[2][0] = fma2(av1.x, bv0.x, acc[2][0]);
                        acc[2][1] = fma2(av1.x, bv0.y, acc[2][1]);
                        acc[2][2] = fma2(av1.x, bv1.x, acc[2][2]);
                        acc[2][3] = fma2(av1.x, bv1.y, acc[2][3]);
                        acc[3][0] = fma2(av1.y, bv0.x, acc[3][0]);
                        acc[3][1] = fma2(av1.y, bv0.y, acc[3][1]);
                        acc[3][2] = fma2(av1.y, bv1.x, acc[3][2]);
                        acc[3][3] = fma2(av1.y, bv1.y, acc[3][3]);
                    }
                    if (cc < DIMX / BK - 1) {
                        const int nxt = cur ^ 1;
                        sh_As[nxt][ak + 0][arow] = a0r.x;
                        sh_As[nxt][ak + 1][arow] = a0r.y;
                        sh_As[nxt][ak + 2][arow] = a0r.z;
                        sh_As[nxt][ak + 3][arow] = a0r.w;
                        if (tid < 128) {
                            sh_As[nxt][ak + 0][arow + 96] = a1r.x;
                            sh_As[nxt][ak + 1][arow + 96] = a1r.y;
                            sh_As[nxt][ak + 2][arow + 96] = a1r.z;
                            sh_As[nxt][ak + 3][arow + 96] = a1r.w;
                        }
                        ulonglong2 bp0, bp1;
                        bp0.x = pk2(b0r.x, b0r.x); bp0.y = pk2(b0r.y, b0r.y);
                        bp1.x = pk2(b0r.z, b0r.z); bp1.y = pk2(b0r.w, b0r.w);
                        *(ulonglong2*)&sh_Bs[nxt][brow][bc] = bp0;
                        *(ulonglong2*)&sh_Bs[nxt][brow][bc + 2] = bp1;
                        __syncthreads();
                    }
                }

#pragma unroll
                for (int mp = 0; mp < 4; mp++) {
                    float l0, h0, l1, h1, l2, h2, l3, h3;
                    up2(acc[mp][0], l0, h0);
                    up2(acc[mp][1], l1, h1);
                    up2(acc[mp][2], l2, h2);
                    up2(acc[mp][3], l3, h3);
                    const int row = ty8 + 2 * mp;
                    *(float4*)&Ct[(size_t)row * G3 + tx4] =
                        make_float4(l0, l1, l2, l3);
                    *(float4*)&Ct[(size_t)(row + 1) * G3 + tx4] =
                        make_float4(h0, h1, h2, h3);
                }
                __syncthreads();
                if (tid == 0) {
                    __threadfence();
                    atomicAdd(&g_xgready[l][dir][b][ci], 1u);
                }
                __syncthreads();
            }
        }
    }
}

// ---------------------------------------------------------------------------
extern "C" void kernel_launch(void* const* d_in, const int* in_sizes, int n_in,
                              void* d_out, int out_size) {
    const float* x  = (const float*)d_in[0];
    const float* Wi = (const float*)d_in[1];
    const float* Wh = (const float*)d_in[2];
    const float* bh = (const float*)d_in[3];
    float* out = (float*)d_out;

    reset_flags<<<(NLAYER * 2 * BATCH * NCHUNK + 255) / 256, 256>>>();
    fused_birnn<<<NBLK, 384>>>(x, Wi, Wh, bh, out);
}